// round 1
// baseline (speedup 1.0000x reference)
#include <cuda_runtime.h>

// SignalDualBackground: out[b,c,s,t] = (1 - spikes[b,c,s,t]) * stat[b,c,t]
//   x[b,c,t]   = mean_s spikes[b,c,s,t]
//   stat[.,t]  = beta*stat[.,t-1] + (1-beta)*x[.,t],  stat[.,-1] = 0
//
// Layout: spikes index = ((b*C + c)*S + s)*T + t, S=64, T=1024.
// One CTA per (b,c): 256 threads, each thread owns 4 consecutive t (float4).
// Linear-recurrence parallel scan via (m,a) composition (shuffle Kogge-Stone).
// Dynamic-smem padding caps occupancy at 2 CTAs/SM so the phase-3 re-read of
// the 256KB tile stays resident in L2 (296 CTAs * 256KB = 75MB < 126MB L2).

#define T_DIM 1024
#define S_DIM 64
#define THREADS 256
#define T4 (T_DIM / 4)          // 256 float4 per row
#define PAD_SMEM (80 * 1024)    // occupancy limiter: 2 CTAs/SM

__global__ __launch_bounds__(THREADS)
void sdb_kernel(const float4* __restrict__ sp,
                const float* __restrict__ beta_p,
                float4* __restrict__ out) {
    extern __shared__ float smem_pad[];   // unused; occupancy limiter
    (void)smem_pad;
    __shared__ float Ms[8], As[8];

    const int tid  = threadIdx.x;
    const int lane = tid & 31;
    const int wid  = tid >> 5;

    const size_t base = (size_t)blockIdx.x * (S_DIM * T4);
    const float4* spb = sp + base;
    float4* ob = out + base;

    const float beta = beta_p[0];
    const float omb  = 1.0f - beta;

    // ---------- Phase 1: mean over synapses ----------
    float4 sum = make_float4(0.f, 0.f, 0.f, 0.f);
    #pragma unroll 16
    for (int s = 0; s < S_DIM; ++s) {
        float4 v = spb[s * T4 + tid];
        sum.x += v.x; sum.y += v.y; sum.z += v.z; sum.w += v.w;
    }
    const float inv = 1.0f / (float)S_DIM;
    const float x0 = sum.x * inv, x1 = sum.y * inv;
    const float x2 = sum.z * inv, x3 = sum.w * inv;

    // ---------- Phase 2: parallel linear-recurrence scan ----------
    // per-thread composite over its 4 elements: state' = m*state + a
    float a = omb * x0;
    a = beta * a + omb * x1;
    a = beta * a + omb * x2;
    a = beta * a + omb * x3;
    float m = beta * beta;
    m = m * m;                    // beta^4

    // warp inclusive scan of (m, a)
    #pragma unroll
    for (int d = 1; d < 32; d <<= 1) {
        float ap = __shfl_up_sync(0xffffffffu, a, d);
        float mp = __shfl_up_sync(0xffffffffu, m, d);
        if (lane >= d) { a += m * ap; m *= mp; }
    }
    if (lane == 31) { Ms[wid] = m; As[wid] = a; }
    __syncthreads();

    // block scan of the 8 warp aggregates (lanes 0..7 of warp 0)
    if (tid < 8) {
        float a2 = As[tid], m2 = Ms[tid];
        #pragma unroll
        for (int d = 1; d < 8; d <<= 1) {
            float ap = __shfl_up_sync(0x000000ffu, a2, d);
            float mp = __shfl_up_sync(0x000000ffu, m2, d);
            if (tid >= d) { a2 += m2 * ap; m2 *= mp; }
        }
        As[tid] = a2; Ms[tid] = m2;
    }
    __syncthreads();

    // full inclusive value for this thread's last element
    const float warp_pref = (wid > 0) ? As[wid - 1] : 0.0f;
    const float a_full = a + m * warp_pref;
    // exclusive prefix = previous thread's full inclusive
    const float a_prev = __shfl_up_sync(0xffffffffu, a_full, 1);
    const float a_excl = (lane > 0) ? a_prev : warp_pref;

    // re-run the 4-step recurrence from the exclusive prefix
    float st = a_excl;
    st = beta * st + omb * x0; const float s0 = st;
    st = beta * st + omb * x1; const float s1 = st;
    st = beta * st + omb * x2; const float s2 = st;
    st = beta * st + omb * x3; const float s3 = st;

    // ---------- Phase 3: broadcast output (re-read tile; L2-resident) ----------
    #pragma unroll 8
    for (int s = 0; s < S_DIM; ++s) {
        float4 v = spb[s * T4 + tid];
        float4 o;
        o.x = (1.0f - v.x) * s0;
        o.y = (1.0f - v.y) * s1;
        o.z = (1.0f - v.z) * s2;
        o.w = (1.0f - v.w) * s3;
        ob[s * T4 + tid] = o;
    }
}

extern "C" void kernel_launch(void* const* d_in, const int* in_sizes, int n_in,
                              void* d_out, int out_size) {
    const float* spikes = (const float*)d_in[0];
    const float* beta   = (const float*)d_in[1];
    float* out          = (float*)d_out;

    const int nbc = in_sizes[0] / (S_DIM * T_DIM);  // 16*128 = 2048

    cudaFuncSetAttribute(sdb_kernel,
                         cudaFuncAttributeMaxDynamicSharedMemorySize, PAD_SMEM);
    sdb_kernel<<<nbc, THREADS, PAD_SMEM>>>(
        (const float4*)spikes, beta, (float4*)out);
}

// round 2
// speedup vs baseline: 1.3268x; 1.3268x over previous
#include <cuda_runtime.h>

// SignalDualBackground: out[b,c,s,t] = (1 - spikes[b,c,s,t]) * stat[b,c,t]
//   x[b,c,t]  = mean_s spikes[b,c,s,t]         (S=64)
//   stat[.,t] = beta*stat[.,t-1] + (1-beta)*x[.,t], stat[.,-1]=0  (T=1024)
//
// R2 design: one 1024-thread CTA per (b,c), 1 CTA/SM (smem pad) so the
// concurrent L2 footprint is 148 * 256KB = 38MB << 126MB L2 -> the phase-3
// re-read of the tile hits L2. 32 warps/SM for DRAM latency hiding.
// Thread (part, col): part = tid>>8 owns 16 synapse rows, col = tid&255 owns
// one float4 time chunk. Synapse partials reduced through smem; the linear
// recurrence is scanned in parallel by warps 0..7 via (m,a) composition.

#define T_DIM 1024
#define S_DIM 64
#define THREADS 1024
#define T4 (T_DIM / 4)            // 256 float4 per row
#define S_PER_PART 16             // 64 synapses / 4 parts
#define PAD_SMEM (100 * 1024)     // static(~20KB) + pad > 114KB -> 1 CTA/SM

__global__ __launch_bounds__(THREADS, 1)
void sdb_kernel(const float4* __restrict__ sp,
                const float* __restrict__ beta_p,
                float4* __restrict__ out) {
    extern __shared__ float smem_pad[];   // occupancy limiter
    (void)smem_pad;
    __shared__ float4 red[THREADS];       // 16 KB: synapse partials
    __shared__ float4 statS[T4];          // 4 KB: broadcast stat
    __shared__ float Ms[8], As[8];

    const int tid  = threadIdx.x;
    const int col  = tid & (T4 - 1);      // time-chunk index 0..255
    const int part = tid >> 8;            // synapse partition 0..3
    const int s0r  = part * S_PER_PART;

    const size_t base = (size_t)blockIdx.x * (S_DIM * T4);
    const float4* spb = sp + base;
    float4* ob = out + base;

    const float beta = beta_p[0];
    const float omb  = 1.0f - beta;

    // ---------- Phase 1: partial sums over 16 synapse rows ----------
    float4 sum = make_float4(0.f, 0.f, 0.f, 0.f);
    #pragma unroll
    for (int k = 0; k < S_PER_PART; ++k) {
        float4 v = spb[(s0r + k) * T4 + col];
        sum.x += v.x; sum.y += v.y; sum.z += v.z; sum.w += v.w;
    }
    red[tid] = sum;
    __syncthreads();

    // ---------- Phase 2: finish mean + parallel scan (warps 0..7) ----------
    if (part == 0) {
        const int lane = tid & 31;
        const int wid  = tid >> 5;        // 0..7

        float4 a4 = red[col];
        float4 b4 = red[col + 256];
        float4 c4 = red[col + 512];
        float4 d4 = red[col + 768];
        const float inv = 1.0f / (float)S_DIM;
        const float x0 = (a4.x + b4.x + c4.x + d4.x) * inv;
        const float x1 = (a4.y + b4.y + c4.y + d4.y) * inv;
        const float x2 = (a4.z + b4.z + c4.z + d4.z) * inv;
        const float x3 = (a4.w + b4.w + c4.w + d4.w) * inv;

        // per-thread composite over 4 time steps: state' = m*state + a
        float a = omb * x0;
        a = beta * a + omb * x1;
        a = beta * a + omb * x2;
        a = beta * a + omb * x3;
        float m = beta * beta;
        m = m * m;                        // beta^4

        // warp inclusive scan of (m, a)
        #pragma unroll
        for (int d = 1; d < 32; d <<= 1) {
            float ap = __shfl_up_sync(0xffffffffu, a, d);
            float mp = __shfl_up_sync(0xffffffffu, m, d);
            if (lane >= d) { a += m * ap; m *= mp; }
        }
        if (lane == 31) { Ms[wid] = m; As[wid] = a; }
        __syncwarp();
        // cross-warp scan (8 aggregates) done redundantly per warp via smem
        __threadfence_block();
        // need all 8 warp aggregates visible: lightweight barrier over 8 warps
        // simplest correct option: full block sync
        // (cheap: once per CTA)
        // NOTE: other 24 warps also hit this barrier below.
        // fallthrough to block-wide sync
        // -- handled outside the if --
        // compute after sync (see below)
        // store per-thread partials for after-sync continuation
        red[tid] = make_float4(a, m, x0, x1);
        statS[col] = make_float4(x2, x3, 0.f, 0.f);
    }
    __syncthreads();

    if (part == 0) {
        const int lane = tid & 31;
        const int wid  = tid >> 5;

        float4 saved = red[tid];
        float a = saved.x, m = saved.y;
        const float x0 = saved.z, x1 = saved.w;
        float4 saved2 = statS[col];
        const float x2 = saved2.x, x3 = saved2.y;

        // scan the 8 warp aggregates serially in registers (tiny)
        float pref = 0.0f;
        #pragma unroll
        for (int w = 0; w < 8; ++w) {
            if (w == wid) break;
            pref = Ms[w] * pref + As[w];  // wait: order -- see note
        }
        // NOTE: aggregates compose left-to-right: state after warp w block is
        // M_w * state + A_w. pref after warps [0..wid-1] computed above.

        const float a_full = a + m * pref;
        const float a_prev = __shfl_up_sync(0xffffffffu, a_full, 1);
        const float a_excl = (lane > 0) ? a_prev : pref;

        float st = a_excl;
        st = beta * st + omb * x0; const float r0 = st;
        st = beta * st + omb * x1; const float r1 = st;
        st = beta * st + omb * x2; const float r2 = st;
        st = beta * st + omb * x3; const float r3 = st;

        statS[col] = make_float4(r0, r1, r2, r3);
    }
    __syncthreads();

    // ---------- Phase 3: broadcast output (re-read tile; L2 hit) ----------
    const float4 st4 = statS[col];
    #pragma unroll
    for (int k = 0; k < S_PER_PART; ++k) {
        const size_t idx = (size_t)(s0r + k) * T4 + col;
        float4 v = __ldcs(&spb[idx]);         // last use: evict-first
        float4 o;
        o.x = (1.0f - v.x) * st4.x;
        o.y = (1.0f - v.y) * st4.y;
        o.z = (1.0f - v.z) * st4.z;
        o.w = (1.0f - v.w) * st4.w;
        __stcs(&ob[idx], o);                  // streaming store
    }
}

extern "C" void kernel_launch(void* const* d_in, const int* in_sizes, int n_in,
                              void* d_out, int out_size) {
    const float* spikes = (const float*)d_in[0];
    const float* beta   = (const float*)d_in[1];
    float* out          = (float*)d_out;

    const int nbc = in_sizes[0] / (S_DIM * T_DIM);  // 16*128 = 2048

    cudaFuncSetAttribute(sdb_kernel,
                         cudaFuncAttributeMaxDynamicSharedMemorySize, PAD_SMEM);
    sdb_kernel<<<nbc, THREADS, PAD_SMEM>>>(
        (const float4*)spikes, beta, (float4*)out);
}